// round 1
// baseline (speedup 1.0000x reference)
#include <cuda_runtime.h>
#include <math.h>

#define T_STEPS 256
#define BATCH   256
#define IN_DIM  512
#define H_DIM   512
#define GATES   2048   // 4*H

// ---------------- scratch (device globals: allocation-free rule) ----------
__device__ float g_Xg[(size_t)T_STEPS * BATCH * GATES];   // x @ W_ih^T + b, 512 MB
__device__ float g_h[2][BATCH * H_DIM];                   // double-buffered hidden
__device__ float g_c[BATCH * H_DIM];                      // cell state

// ---------------- init: zero recurrent state each run ---------------------
__global__ void zero_state_kernel() {
    int i = blockIdx.x * blockDim.x + threadIdx.x;
    if (i < BATCH * H_DIM) { g_h[0][i] = 0.f; g_c[i] = 0.f; }
}

// ---------------- kernel 1: Xg = x @ W_ih^T + (b_ih + b_hh) ---------------
// A [M=65536, K=512] row-major (x), B [N=2048, K=512] row-major (W_ih).
// C[m,n] = sum_k A[m,k]*B[n,k] + bias[n].
#define TM 64
#define TN 64
#define TK 32

__global__ __launch_bounds__(256) void xgemm_kernel(
    const float* __restrict__ x,
    const float* __restrict__ Wih,
    const float* __restrict__ bih,
    const float* __restrict__ bhh)
{
    __shared__ float As[TK][TM + 1];   // [k][m], pad 1 -> conflict-free
    __shared__ float Bs[TK][TN + 1];   // [k][n]
    const int m0 = blockIdx.y * TM;
    const int n0 = blockIdx.x * TN;
    const int tid = threadIdx.x;
    const int tx = tid & 15;
    const int ty = tid >> 4;

    float acc[4][4] = {};

    for (int k0 = 0; k0 < IN_DIM; k0 += TK) {
        #pragma unroll
        for (int i = 0; i < 8; i++) {
            int idx = tid + i * 256;      // 2048 elems per tile
            int r = idx >> 5;             // row within tile (0..63)
            int c = idx & 31;             // k within chunk
            As[c][r] = x  [(size_t)(m0 + r) * IN_DIM + k0 + c];
            Bs[c][r] = Wih[(size_t)(n0 + r) * IN_DIM + k0 + c];
        }
        __syncthreads();
        #pragma unroll
        for (int kk = 0; kk < TK; kk++) {
            float a[4], b[4];
            #pragma unroll
            for (int i = 0; i < 4; i++) a[i] = As[kk][ty * 4 + i];
            #pragma unroll
            for (int j = 0; j < 4; j++) b[j] = Bs[kk][tx * 4 + j];
            #pragma unroll
            for (int i = 0; i < 4; i++)
                #pragma unroll
                for (int j = 0; j < 4; j++)
                    acc[i][j] += a[i] * b[j];
        }
        __syncthreads();
    }

    #pragma unroll
    for (int j = 0; j < 4; j++) {
        int n = n0 + tx * 4 + j;
        float bias = bih[n] + bhh[n];
        #pragma unroll
        for (int i = 0; i < 4; i++) {
            int m = m0 + ty * 4 + i;
            g_Xg[(size_t)m * GATES + n] = acc[i][j] + bias;
        }
    }
}

// ---------------- kernel 2: one LSTM step (recurrent GEMM + gates fused) --
// Block computes a [32 b x 32 hh] tile for ALL FOUR gates (cols g*512+hh),
// so the elementwise update is fully local. h double-buffered across steps.
__device__ __forceinline__ float sigmoidf_(float v) {
    return 1.0f / (1.0f + expf(-v));
}

__global__ __launch_bounds__(256) void lstm_step_kernel(
    const float* __restrict__ Whh,      // [2048, 512]
    const int*   __restrict__ dones,    // [T, B]
    float* __restrict__ out_lstm,       // [T, B, H]
    float* __restrict__ out_hidden,     // [T, 2, B, H]
    int t)
{
    __shared__ float h_s[TK][32 + 1];        // [k][b]
    __shared__ float W_s[4][TK][32 + 1];     // [gate][k][hh]

    const float* h_in  = g_h[t & 1];
    float*       h_out = g_h[(t + 1) & 1];

    const int hh0 = blockIdx.x * 32;
    const int b0  = blockIdx.y * 32;
    const int tid = threadIdx.x;
    const int tb  = tid >> 5;    // warp id 0..7  -> 4 batch rows each
    const int thh = tid & 31;    // lane          -> 1 hh column

    float acc[4][4] = {};        // [gate][b-sub]

    for (int k0 = 0; k0 < H_DIM; k0 += TK) {
        // h tile: 32 b x 32 k, apply done-reset while loading
        #pragma unroll
        for (int i = 0; i < 4; i++) {
            int idx = tid + i * 256;
            int b = idx >> 5;
            int k = idx & 31;
            float keep = 1.0f - (float)dones[t * BATCH + b0 + b];
            h_s[k][b] = h_in[(b0 + b) * H_DIM + k0 + k] * keep;
        }
        // W tile: 4 gates x 32 hh rows x 32 k
        #pragma unroll
        for (int i = 0; i < 16; i++) {
            int idx = tid + i * 256;
            int k = idx & 31;
            int r = idx >> 5;           // 0..127
            int g = r >> 5;
            int hh = r & 31;
            W_s[g][k][hh] =
                Whh[(size_t)(g * H_DIM + hh0 + hh) * H_DIM + k0 + k];
        }
        __syncthreads();
        #pragma unroll
        for (int kk = 0; kk < TK; kk++) {
            float hv[4], wv[4];
            #pragma unroll
            for (int i = 0; i < 4; i++) hv[i] = h_s[kk][tb * 4 + i];   // broadcast
            #pragma unroll
            for (int g = 0; g < 4; g++) wv[g] = W_s[g][kk][thh];       // conflict-free
            #pragma unroll
            for (int g = 0; g < 4; g++)
                #pragma unroll
                for (int i = 0; i < 4; i++)
                    acc[g][i] += hv[i] * wv[g];
        }
        __syncthreads();
    }

    // Epilogue: gates -> nonlinearities -> state update -> 3 output writes
    const int hh = hh0 + thh;
    const float* xg_t = g_Xg + (size_t)t * BATCH * GATES;

    #pragma unroll
    for (int i = 0; i < 4; i++) {
        int b = b0 + tb * 4 + i;
        const float* xg = xg_t + (size_t)b * GATES;

        float gi = acc[0][i] + xg[0 * H_DIM + hh];
        float gf = acc[1][i] + xg[1 * H_DIM + hh];
        float gg = acc[2][i] + xg[2 * H_DIM + hh];
        float go = acc[3][i] + xg[3 * H_DIM + hh];

        float keep = 1.0f - (float)dones[t * BATCH + b];
        float hp = h_in[b * H_DIM + hh] * keep;   // pre (reset) hidden
        float cp = g_c [b * H_DIM + hh] * keep;   // pre (reset) cell

        float ig = sigmoidf_(gi);
        float fg = sigmoidf_(gf);
        float gt = tanhf(gg);
        float og = sigmoidf_(go);

        float cn = fg * cp + ig * gt;
        float hn = og * tanhf(cn);

        out_hidden[(((size_t)t * 2 + 0) * BATCH + b) * H_DIM + hh] = hp;
        out_hidden[(((size_t)t * 2 + 1) * BATCH + b) * H_DIM + hh] = cp;
        out_lstm  [((size_t)t * BATCH + b) * H_DIM + hh]           = hn;

        h_out[b * H_DIM + hh] = hn;
        g_c  [b * H_DIM + hh] = cn;
    }
}

// ---------------- launch ---------------------------------------------------
extern "C" void kernel_launch(void* const* d_in, const int* in_sizes, int n_in,
                              void* d_out, int out_size) {
    const float* x     = (const float*)d_in[0];   // [T, B, IN]
    const int*   dones = (const int*)  d_in[1];   // [T, B]
    const float* Wih   = (const float*)d_in[2];   // [4H, IN]
    const float* Whh   = (const float*)d_in[3];   // [4H, H]
    const float* bih   = (const float*)d_in[4];   // [4H]
    const float* bhh   = (const float*)d_in[5];   // [4H]

    float* out_lstm   = (float*)d_out;                                  // T*B*H
    float* out_hidden = (float*)d_out + (size_t)T_STEPS * BATCH * H_DIM; // T*2*B*H

    zero_state_kernel<<<(BATCH * H_DIM + 255) / 256, 256>>>();

    dim3 g1(GATES / TN, (T_STEPS * BATCH) / TM);   // (32, 1024)
    xgemm_kernel<<<g1, 256>>>(x, Wih, bih, bhh);

    dim3 gs(H_DIM / 32, BATCH / 32);               // (16, 8)
    for (int t = 0; t < T_STEPS; t++) {
        lstm_step_kernel<<<gs, 256>>>(Whh, dones, out_lstm, out_hidden, t);
    }
}

// round 2
// speedup vs baseline: 2.4262x; 2.4262x over previous
#include <cuda_runtime.h>
#include <math.h>
#include <stdint.h>

#define T_STEPS 256
#define BATCH   256
#define IN_DIM  512
#define H_DIM   512
#define GATES   2048
#define NBLK    128

// ---------------- device scratch (no allocs allowed) ----------------------
__device__ float g_Xg[(size_t)T_STEPS * BATCH * GATES];    // x @ Wih^T + b (512MB)
__device__ float g_h[2][BATCH * H_DIM];                    // double-buffered hidden
__device__ float g_Wp_hh[64 * 2048 * 8];                   // tf32-packed W_hh frags
__device__ float g_Wp_ih[64 * 2048 * 8];                   // tf32-packed W_ih frags
__device__ unsigned g_bar_count = 0;
__device__ volatile unsigned g_bar_gen = 0;

// ---------------- helpers --------------------------------------------------
__device__ __forceinline__ float f2tf32f(float f) {
    unsigned r;
    asm("cvt.rna.tf32.f32 %0, %1;" : "=r"(r) : "f"(f));
    return __uint_as_float(r);
}

__device__ __forceinline__ void mma_tf32(float* c,
    unsigned a0, unsigned a1, unsigned a2, unsigned a3,
    unsigned b0, unsigned b1)
{
    asm volatile(
        "mma.sync.aligned.m16n8k8.row.col.f32.tf32.tf32.f32 "
        "{%0,%1,%2,%3},{%4,%5,%6,%7},{%8,%9},{%0,%1,%2,%3};"
        : "+f"(c[0]), "+f"(c[1]), "+f"(c[2]), "+f"(c[3])
        : "r"(a0), "r"(a1), "r"(a2), "r"(a3), "r"(b0), "r"(b1));
}

__device__ __forceinline__ float sigm(float v) { return 1.0f / (1.0f + expf(-v)); }

// ---------------- prep: pack W into tf32 fragment order -------------------
// Wp[kb][n][p][hi] = tf32(W[n][kb*8 + p + 4*hi]),  p=k%4, hi=(k%8)/4
__global__ void prep_kernel(const float* __restrict__ Wih,
                            const float* __restrict__ Whh) {
    int idx = blockIdx.x * blockDim.x + threadIdx.x;   // 0 .. 2*2^20-1
    int which = idx >> 20;
    int r = idx & 1048575;          // n*512 + k
    int n = r >> 9, k = r & 511;
    const float* W = which ? Whh : Wih;
    float* dst = which ? g_Wp_hh : g_Wp_ih;
    int kb = k >> 3, p = k & 3, hi = (k >> 2) & 1;
    dst[(((size_t)kb * 2048 + n) * 4 + p) * 2 + hi] = f2tf32f(W[r]);
}

// ---------------- A-tile staging into fragment-permuted smem --------------
// Ap layout: [kb(64)][lane(32)][12 pad]  (j = 4*mt + 2*jk + b8) -> one
// LDS.128 per m16 fragment, conflict-free (stride 12 words).
// thread t stages row b=t/8, k-range (t%8)*64..+63.
#define AP_WORDS (64 * 32 * 12)

template <bool ZERO, bool CG>
__device__ __forceinline__ void stage_A(float* Ap, const float* src_row,
                                        float scale, int tid) {
    int b  = tid >> 3;
    int kc = tid & 7;
    const float4* src = (const float4*)(src_row + kc * 64);
    #pragma unroll
    for (int v = 0; v < 16; v++) {
        float4 hv;
        if (ZERO) hv = make_float4(0.f, 0.f, 0.f, 0.f);
        else if (CG) hv = __ldcg(src + v);
        else hv = __ldg(src + v);
        float vals[4] = {hv.x * scale, hv.y * scale, hv.z * scale, hv.w * scale};
        int kbase = kc * 64 + v * 4;
        #pragma unroll
        for (int e = 0; e < 4; e++) {
            int k = kbase + e;
            int kb = k >> 3;
            int l  = ((b & 7) << 2) | (k & 3);
            int j  = ((b >> 4) << 2) | (((k >> 2) & 1) << 1) | ((b >> 3) & 1);
            Ap[(kb * 32 + l) * 12 + j] = f2tf32f(vals[e]);
        }
    }
}

// ---------------- kernel 1: Xg = x @ Wih^T + (bih+bhh), tf32 MMA ----------
// block tile: m=32 rows of x, n=128 cols. 8 warps: warp w -> n range w*16.
extern __shared__ float sm_dyn[];

__global__ __launch_bounds__(256, 2) void xgemm_tc(
    const float* __restrict__ x,
    const float* __restrict__ bih,
    const float* __restrict__ bhh)
{
    float* Ap = sm_dyn;
    const int tid = threadIdx.x, lane = tid & 31, w = tid >> 5;
    const int n0 = blockIdx.x * 128;
    const int m0 = blockIdx.y * 32;

    stage_A<false, false>(Ap, x + (size_t)(m0 + (tid >> 3)) * IN_DIM, 1.0f, tid);
    __syncthreads();

    float acc[2][2][4] = {};          // [mt][nt][creg]
    const int nw = n0 + w * 16;
    const float2* Wp = (const float2*)g_Wp_ih;

    #pragma unroll 4
    for (int kb = 0; kb < 64; kb++) {
        float4 A0 = *(float4*)&Ap[(kb * 32 + lane) * 12];
        float4 A1 = *(float4*)&Ap[(kb * 32 + lane) * 12 + 4];
        unsigned a0x = __float_as_uint(A0.x), a0y = __float_as_uint(A0.y);
        unsigned a0z = __float_as_uint(A0.z), a0w = __float_as_uint(A0.w);
        unsigned a1x = __float_as_uint(A1.x), a1y = __float_as_uint(A1.y);
        unsigned a1z = __float_as_uint(A1.z), a1w = __float_as_uint(A1.w);
        #pragma unroll
        for (int nt = 0; nt < 2; nt++) {
            int n = nw + nt * 8 + (lane >> 2);
            float2 bv = Wp[((size_t)kb * 2048 + n) * 4 + (lane & 3)];
            unsigned b0 = __float_as_uint(bv.x), b1 = __float_as_uint(bv.y);
            mma_tf32(acc[0][nt], a0x, a0y, a0z, a0w, b0, b1);
            mma_tf32(acc[1][nt], a1x, a1y, a1z, a1w, b0, b1);
        }
    }

    #pragma unroll
    for (int nt = 0; nt < 2; nt++) {
        int nc = nw + nt * 8 + (lane & 3) * 2;
        float bs0 = __ldg(&bih[nc]) + __ldg(&bhh[nc]);
        float bs1 = __ldg(&bih[nc + 1]) + __ldg(&bhh[nc + 1]);
        #pragma unroll
        for (int mt = 0; mt < 2; mt++) {
            int r0 = m0 + mt * 16 + (lane >> 2);
            float2 v0 = make_float2(acc[mt][nt][0] + bs0, acc[mt][nt][1] + bs1);
            float2 v1 = make_float2(acc[mt][nt][2] + bs0, acc[mt][nt][3] + bs1);
            *(float2*)&g_Xg[(size_t)r0 * GATES + nc]        = v0;
            *(float2*)&g_Xg[(size_t)(r0 + 8) * GATES + nc]  = v1;
        }
    }
}

// ---------------- grid-wide barrier (all 128 blocks resident) -------------
__device__ __forceinline__ void grid_sync() {
    __syncthreads();
    if (threadIdx.x == 0) {
        __threadfence();
        unsigned snap = g_bar_gen;
        unsigned arrived = atomicAdd(&g_bar_count, 1u);
        if (arrived == gridDim.x - 1) {
            g_bar_count = 0;
            __threadfence();
            g_bar_gen = snap + 1;
        } else {
            while (g_bar_gen == snap) __nanosleep(32);
        }
    }
    __syncthreads();
}

// ---------------- kernel 2: persistent LSTM recurrence --------------------
// 128 blocks = 16 hh-tiles x 8 b-tiles, each 32b x 32hh x 4 gates.
// 8 warps: warp w -> (gate pair gp=w>>2, hh group hg=w&3), m=32 (2 m16 frags).
// c and h state live in registers (block owns its tile). h exchanged via
// global double buffer + grid barrier each step.
__global__ __launch_bounds__(256, 1) void lstm_tc(
    const int*  __restrict__ dones,
    float* __restrict__ out_lstm,       // [T,B,H]
    float* __restrict__ out_hidden)     // [T,2,B,H]
{
    float* Ap  = sm_dyn;                 // 24576 words
    float* Acc = sm_dyn + AP_WORDS;      // [4][32][36] words

    const int tid = threadIdx.x, lane = tid & 31, w = tid >> 5;
    const int hh0 = (blockIdx.x & 15) * 32;
    const int b0  = (blockIdx.x >> 4) * 32;
    const int gp = w >> 2, hg = w & 3;
    const int eb  = tid >> 3;            // epilogue row (== staging row)
    const int ehh = (tid & 7) * 4;       // epilogue 4 consecutive hh

    float h_st[4] = {0.f, 0.f, 0.f, 0.f};
    float c_st[4] = {0.f, 0.f, 0.f, 0.f};

    const float2* Wp = (const float2*)g_Wp_hh;

    for (int st = 0; st < T_STEPS; st++) {
        // prefetch xg + done mask for epilogue (hidden under the k-loop)
        float4 xv[4];
        {
            const float* xg = g_Xg + ((size_t)st * BATCH + (b0 + eb)) * GATES
                            + hh0 + ehh;
            #pragma unroll
            for (int g = 0; g < 4; g++)
                xv[g] = __ldg((const float4*)(xg + g * 512));
        }
        const float keep = 1.0f - (float)__ldg(&dones[st * BATCH + b0 + eb]);

        // stage masked h into fragment-permuted smem (L2-only: L1 is stale)
        if (st == 0)
            stage_A<true, true>(Ap, (const float*)0, 0.0f, tid);
        else
            stage_A<false, true>(Ap,
                g_h[st & 1] + (size_t)(b0 + eb) * H_DIM, keep, tid);
        __syncthreads();

        float acc[2][2][4] = {};         // [gate-in-pair][mt][creg]
        #pragma unroll 4
        for (int kb = 0; kb < 64; kb++) {
            float4 A0 = *(float4*)&Ap[(kb * 32 + lane) * 12];
            float4 A1 = *(float4*)&Ap[(kb * 32 + lane) * 12 + 4];
            unsigned a0x = __float_as_uint(A0.x), a0y = __float_as_uint(A0.y);
            unsigned a0z = __float_as_uint(A0.z), a0w = __float_as_uint(A0.w);
            unsigned a1x = __float_as_uint(A1.x), a1y = __float_as_uint(A1.y);
            unsigned a1z = __float_as_uint(A1.z), a1w = __float_as_uint(A1.w);
            #pragma unroll
            for (int gi = 0; gi < 2; gi++) {
                int n = (gp * 2 + gi) * 512 + hh0 + hg * 8 + (lane >> 2);
                float2 bv = Wp[((size_t)kb * 2048 + n) * 4 + (lane & 3)];
                unsigned b0r = __float_as_uint(bv.x), b1r = __float_as_uint(bv.y);
                mma_tf32(acc[gi][0], a0x, a0y, a0z, a0w, b0r, b1r);
                mma_tf32(acc[gi][1], a1x, a1y, a1z, a1w, b0r, b1r);
            }
        }

        // exchange accumulators through smem so each thread gets all 4 gates
        #pragma unroll
        for (int gi = 0; gi < 2; gi++) {
            int g  = gp * 2 + gi;
            int hc = hg * 8 + (lane & 3) * 2;
            #pragma unroll
            for (int mt = 0; mt < 2; mt++) {
                int bl = mt * 16 + (lane >> 2);
                *(float2*)&Acc[(g * 32 + bl) * 36 + hc] =
                    make_float2(acc[gi][mt][0], acc[gi][mt][1]);
                *(float2*)&Acc[(g * 32 + bl + 8) * 36 + hc] =
                    make_float2(acc[gi][mt][2], acc[gi][mt][3]);
            }
        }
        __syncthreads();

        // epilogue: thread owns (b0+eb, hh0+ehh..+3); state in registers
        float4 ag[4];
        #pragma unroll
        for (int g = 0; g < 4; g++)
            ag[g] = *(float4*)&Acc[(g * 32 + eb) * 36 + ehh];

        float4 hp4, cp4, hn4;
        float* hpf = &hp4.x; float* cpf = &cp4.x; float* hnf = &hn4.x;
        #pragma unroll
        for (int i = 0; i < 4; i++) {
            float gv_i = ((float*)&ag[0])[i] + ((float*)&xv[0])[i];
            float gv_f = ((float*)&ag[1])[i] + ((float*)&xv[1])[i];
            float gv_g = ((float*)&ag[2])[i] + ((float*)&xv[2])[i];
            float gv_o = ((float*)&ag[3])[i] + ((float*)&xv[3])[i];

            float hpv = h_st[i] * keep;
            float cpv = c_st[i] * keep;

            float ii = sigm(gv_i);
            float ff = sigm(gv_f);
            float gg = tanhf(gv_g);
            float oo = sigm(gv_o);

            float cnv = ff * cpv + ii * gg;
            float hnv = oo * tanhf(cnv);

            h_st[i] = hnv; c_st[i] = cnv;
            hpf[i] = hpv; cpf[i] = cpv; hnf[i] = hnv;
        }

        const size_t ob = (size_t)(b0 + eb) * H_DIM + hh0 + ehh;
        *(float4*)&out_hidden[(size_t)(st * 2 + 0) * BATCH * H_DIM + ob] = hp4;
        *(float4*)&out_hidden[(size_t)(st * 2 + 1) * BATCH * H_DIM + ob] = cp4;
        *(float4*)&out_lstm  [(size_t)st * BATCH * H_DIM + ob]           = hn4;
        *(float4*)&g_h[(st + 1) & 1][ob]                                 = hn4;

        grid_sync();
    }
}

// ---------------- launch ---------------------------------------------------
extern "C" void kernel_launch(void* const* d_in, const int* in_sizes, int n_in,
                              void* d_out, int out_size) {
    const float* x     = (const float*)d_in[0];
    const int*   dones = (const int*)  d_in[1];
    const float* Wih   = (const float*)d_in[2];
    const float* Whh   = (const float*)d_in[3];
    const float* bih   = (const float*)d_in[4];
    const float* bhh   = (const float*)d_in[5];

    float* out_lstm   = (float*)d_out;
    float* out_hidden = out_lstm + (size_t)T_STEPS * BATCH * H_DIM;

    const int smem_xg   = AP_WORDS * 4;                      // 98304 B
    const int smem_lstm = (AP_WORDS + 4 * 32 * 36) * 4;      // 116736 B
    cudaFuncSetAttribute(xgemm_tc, cudaFuncAttributeMaxDynamicSharedMemorySize,
                         smem_xg);
    cudaFuncSetAttribute(lstm_tc, cudaFuncAttributeMaxDynamicSharedMemorySize,
                         smem_lstm);

    prep_kernel<<<8192, 256>>>(Wih, Whh);

    dim3 gx(GATES / 128, (T_STEPS * BATCH) / 32);            // (16, 2048)
    xgemm_tc<<<gx, 256, smem_xg>>>(x, bih, bhh);

    lstm_tc<<<NBLK, 256, smem_lstm>>>(dones, out_lstm, out_hidden);
}

// round 3
// speedup vs baseline: 2.4336x; 1.0031x over previous
#include <cuda_runtime.h>
#include <math.h>
#include <stdint.h>

#define T_STEPS 256
#define BATCH   256
#define IN_DIM  512
#define H_DIM   512
#define GATES   2048
#define NBLK    128

// ---------------- device scratch (no allocs allowed) ----------------------
__device__ float g_Xg[(size_t)T_STEPS * BATCH * GATES];    // x @ Wih^T + b (512MB)
__device__ float g_h[2][BATCH * H_DIM];                    // double-buffered hidden
__device__ float g_Wp_hh[64 * 2048 * 8];                   // tf32-packed W_hh frags
__device__ float g_Wp_ih[64 * 2048 * 8];                   // tf32-packed W_ih frags
__device__ unsigned g_bar_count = 0;
__device__ volatile unsigned g_bar_gen = 0;

// ---------------- helpers --------------------------------------------------
__device__ __forceinline__ float f2tf32f(float f) {
    unsigned r;
    asm("cvt.rna.tf32.f32 %0, %1;" : "=r"(r) : "f"(f));
    return __uint_as_float(r);
}

__device__ __forceinline__ void mma_tf32(float* c,
    unsigned a0, unsigned a1, unsigned a2, unsigned a3,
    unsigned b0, unsigned b1)
{
    asm volatile(
        "mma.sync.aligned.m16n8k8.row.col.f32.tf32.tf32.f32 "
        "{%0,%1,%2,%3},{%4,%5,%6,%7},{%8,%9},{%0,%1,%2,%3};"
        : "+f"(c[0]), "+f"(c[1]), "+f"(c[2]), "+f"(c[3])
        : "r"(a0), "r"(a1), "r"(a2), "r"(a3), "r"(b0), "r"(b1));
}

__device__ __forceinline__ float sigm(float v) { return 1.0f / (1.0f + expf(-v)); }

// ---------------- prep: pack W into tf32 fragment order -------------------
// Wp[kb][n][p][hi] = tf32(W[n][kb*8 + p + 4*hi]),  p=k%4, hi=(k%8)/4
__global__ void prep_kernel(const float* __restrict__ Wih,
                            const float* __restrict__ Whh) {
    int idx = blockIdx.x * blockDim.x + threadIdx.x;   // 0 .. 2*2^20-1
    int which = idx >> 20;
    int r = idx & 1048575;          // n*512 + k
    int n = r >> 9, k = r & 511;
    const float* W = which ? Whh : Wih;
    float* dst = which ? g_Wp_hh : g_Wp_ih;
    int kb = k >> 3, p = k & 3, hi = (k >> 2) & 1;
    dst[(((size_t)kb * 2048 + n) * 4 + p) * 2 + hi] = f2tf32f(W[r]);
}

// ---------------- A-tile staging into fragment-permuted smem --------------
// Ap layout: [kb(64)][lane(32)][12 pad]  (j = 4*mt + 2*jk + b8) -> one
// LDS.128 per m16 fragment, conflict-free (stride 12 words).
// thread t stages row b=t/8, k-range (t%8)*64..+63.
#define AP_WORDS (64 * 32 * 12)

template <bool ZERO, bool CG>
__device__ __forceinline__ void stage_A(float* Ap, const float* src_row,
                                        float scale, int tid) {
    int b  = tid >> 3;
    int kc = tid & 7;
    const float4* src = (const float4*)(src_row + kc * 64);
    #pragma unroll
    for (int v = 0; v < 16; v++) {
        float4 hv;
        if (ZERO) hv = make_float4(0.f, 0.f, 0.f, 0.f);
        else if (CG) hv = __ldcg(src + v);
        else hv = __ldg(src + v);
        float vals[4] = {hv.x * scale, hv.y * scale, hv.z * scale, hv.w * scale};
        int kbase = kc * 64 + v * 4;
        #pragma unroll
        for (int e = 0; e < 4; e++) {
            int k = kbase + e;
            int kb = k >> 3;
            int l  = ((b & 7) << 2) | (k & 3);
            int j  = ((b >> 4) << 2) | (((k >> 2) & 1) << 1) | ((b >> 3) & 1);
            Ap[(kb * 32 + l) * 12 + j] = f2tf32f(vals[e]);
        }
    }
}

// ---------------- kernel 1: Xg = x @ Wih^T + (bih+bhh), tf32 MMA ----------
// block tile: m=32 rows of x, n=128 cols. 8 warps: warp w -> n range w*16.
extern __shared__ float sm_dyn[];

__global__ __launch_bounds__(256, 2) void xgemm_tc(
    const float* __restrict__ x,
    const float* __restrict__ bih,
    const float* __restrict__ bhh)
{
    float* Ap = sm_dyn;
    const int tid = threadIdx.x, lane = tid & 31, w = tid >> 5;
    const int n0 = blockIdx.x * 128;
    const int m0 = blockIdx.y * 32;

    stage_A<false, false>(Ap, x + (size_t)(m0 + (tid >> 3)) * IN_DIM, 1.0f, tid);
    __syncthreads();

    float acc[2][2][4] = {};          // [mt][nt][creg]
    const int nw = n0 + w * 16;
    const float2* Wp = (const float2*)g_Wp_ih;

    #pragma unroll 4
    for (int kb = 0; kb < 64; kb++) {
        float4 A0 = *(float4*)&Ap[(kb * 32 + lane) * 12];
        float4 A1 = *(float4*)&Ap[(kb * 32 + lane) * 12 + 4];
        unsigned a0x = __float_as_uint(A0.x), a0y = __float_as_uint(A0.y);
        unsigned a0z = __float_as_uint(A0.z), a0w = __float_as_uint(A0.w);
        unsigned a1x = __float_as_uint(A1.x), a1y = __float_as_uint(A1.y);
        unsigned a1z = __float_as_uint(A1.z), a1w = __float_as_uint(A1.w);
        #pragma unroll
        for (int nt = 0; nt < 2; nt++) {
            int n = nw + nt * 8 + (lane >> 2);
            float2 bv = Wp[((size_t)kb * 2048 + n) * 4 + (lane & 3)];
            unsigned b0 = __float_as_uint(bv.x), b1 = __float_as_uint(bv.y);
            mma_tf32(acc[0][nt], a0x, a0y, a0z, a0w, b0, b1);
            mma_tf32(acc[1][nt], a1x, a1y, a1z, a1w, b0, b1);
        }
    }

    #pragma unroll
    for (int nt = 0; nt < 2; nt++) {
        int nc = nw + nt * 8 + (lane & 3) * 2;
        float bs0 = __ldg(&bih[nc]) + __ldg(&bhh[nc]);
        float bs1 = __ldg(&bih[nc + 1]) + __ldg(&bhh[nc + 1]);
        #pragma unroll
        for (int mt = 0; mt < 2; mt++) {
            int r0 = m0 + mt * 16 + (lane >> 2);
            float2 v0 = make_float2(acc[mt][nt][0] + bs0, acc[mt][nt][1] + bs1);
            float2 v1 = make_float2(acc[mt][nt][2] + bs0, acc[mt][nt][3] + bs1);
            *(float2*)&g_Xg[(size_t)r0 * GATES + nc]        = v0;
            *(float2*)&g_Xg[(size_t)(r0 + 8) * GATES + nc]  = v1;
        }
    }
}

// ---------------- grid-wide barrier (all 128 blocks resident) -------------
__device__ __forceinline__ void grid_sync() {
    __syncthreads();
    if (threadIdx.x == 0) {
        __threadfence();
        unsigned snap = g_bar_gen;
        unsigned arrived = atomicAdd(&g_bar_count, 1u);
        if (arrived == gridDim.x - 1) {
            g_bar_count = 0;
            __threadfence();
            g_bar_gen = snap + 1;
        } else {
            while (g_bar_gen == snap) __nanosleep(32);
        }
    }
    __syncthreads();
}

// ---------------- kernel 2: persistent LSTM recurrence --------------------
// 128 blocks = 16 hh-tiles x 8 b-tiles, each 32b x 32hh x 4 gates.
// 8 warps: warp w -> (gate pair gp=w>>2, hh group hg=w&3), m=32 (2 m16 frags).
// c and h state live in registers (block owns its tile). h exchanged via
// global double buffer + grid barrier each step.
__global__ __launch_bounds__(256, 1) void lstm_tc(
    const int*  __restrict__ dones,
    float* __restrict__ out_lstm,       // [T,B,H]
    float* __restrict__ out_hidden)     // [T,2,B,H]
{
    float* Ap  = sm_dyn;                 // 24576 words
    float* Acc = sm_dyn + AP_WORDS;      // [4][32][36] words

    const int tid = threadIdx.x, lane = tid & 31, w = tid >> 5;
    const int hh0 = (blockIdx.x & 15) * 32;
    const int b0  = (blockIdx.x >> 4) * 32;
    const int gp = w >> 2, hg = w & 3;
    const int eb  = tid >> 3;            // epilogue row (== staging row)
    const int ehh = (tid & 7) * 4;       // epilogue 4 consecutive hh

    float h_st[4] = {0.f, 0.f, 0.f, 0.f};
    float c_st[4] = {0.f, 0.f, 0.f, 0.f};

    const float2* Wp = (const float2*)g_Wp_hh;

    for (int st = 0; st < T_STEPS; st++) {
        // prefetch xg + done mask for epilogue (hidden under the k-loop)
        float4 xv[4];
        {
            const float* xg = g_Xg + ((size_t)st * BATCH + (b0 + eb)) * GATES
                            + hh0 + ehh;
            #pragma unroll
            for (int g = 0; g < 4; g++)
                xv[g] = __ldg((const float4*)(xg + g * 512));
        }
        const float keep = 1.0f - (float)__ldg(&dones[st * BATCH + b0 + eb]);

        // stage masked h into fragment-permuted smem (L2-only: L1 is stale)
        if (st == 0)
            stage_A<true, true>(Ap, (const float*)0, 0.0f, tid);
        else
            stage_A<false, true>(Ap,
                g_h[st & 1] + (size_t)(b0 + eb) * H_DIM, keep, tid);
        __syncthreads();

        float acc[2][2][4] = {};         // [gate-in-pair][mt][creg]
        #pragma unroll 4
        for (int kb = 0; kb < 64; kb++) {
            float4 A0 = *(float4*)&Ap[(kb * 32 + lane) * 12];
            float4 A1 = *(float4*)&Ap[(kb * 32 + lane) * 12 + 4];
            unsigned a0x = __float_as_uint(A0.x), a0y = __float_as_uint(A0.y);
            unsigned a0z = __float_as_uint(A0.z), a0w = __float_as_uint(A0.w);
            unsigned a1x = __float_as_uint(A1.x), a1y = __float_as_uint(A1.y);
            unsigned a1z = __float_as_uint(A1.z), a1w = __float_as_uint(A1.w);
            #pragma unroll
            for (int gi = 0; gi < 2; gi++) {
                int n = (gp * 2 + gi) * 512 + hh0 + hg * 8 + (lane >> 2);
                float2 bv = Wp[((size_t)kb * 2048 + n) * 4 + (lane & 3)];
                unsigned b0r = __float_as_uint(bv.x), b1r = __float_as_uint(bv.y);
                mma_tf32(acc[gi][0], a0x, a0y, a0z, a0w, b0r, b1r);
                mma_tf32(acc[gi][1], a1x, a1y, a1z, a1w, b0r, b1r);
            }
        }

        // exchange accumulators through smem so each thread gets all 4 gates
        #pragma unroll
        for (int gi = 0; gi < 2; gi++) {
            int g  = gp * 2 + gi;
            int hc = hg * 8 + (lane & 3) * 2;
            #pragma unroll
            for (int mt = 0; mt < 2; mt++) {
                int bl = mt * 16 + (lane >> 2);
                *(float2*)&Acc[(g * 32 + bl) * 36 + hc] =
                    make_float2(acc[gi][mt][0], acc[gi][mt][1]);
                *(float2*)&Acc[(g * 32 + bl + 8) * 36 + hc] =
                    make_float2(acc[gi][mt][2], acc[gi][mt][3]);
            }
        }
        __syncthreads();

        // epilogue: thread owns (b0+eb, hh0+ehh..+3); state in registers
        float4 ag[4];
        #pragma unroll
        for (int g = 0; g < 4; g++)
            ag[g] = *(float4*)&Acc[(g * 32 + eb) * 36 + ehh];

        float4 hp4, cp4, hn4;
        float* hpf = &hp4.x; float* cpf = &cp4.x; float* hnf = &hn4.x;
        #pragma unroll
        for (int i = 0; i < 4; i++) {
            float gv_i = ((float*)&ag[0])[i] + ((float*)&xv[0])[i];
            float gv_f = ((float*)&ag[1])[i] + ((float*)&xv[1])[i];
            float gv_g = ((float*)&ag[2])[i] + ((float*)&xv[2])[i];
            float gv_o = ((float*)&ag[3])[i] + ((float*)&xv[3])[i];

            float hpv = h_st[i] * keep;
            float cpv = c_st[i] * keep;

            float ii = sigm(gv_i);
            float ff = sigm(gv_f);
            float gg = tanhf(gv_g);
            float oo = sigm(gv_o);

            float cnv = ff * cpv + ii * gg;
            float hnv = oo * tanhf(cnv);

            h_st[i] = hnv; c_st[i] = cnv;
            hpf[i] = hpv; cpf[i] = cpv; hnf[i] = hnv;
        }

        const size_t ob = (size_t)(b0 + eb) * H_DIM + hh0 + ehh;
        *(float4*)&out_hidden[(size_t)(st * 2 + 0) * BATCH * H_DIM + ob] = hp4;
        *(float4*)&out_hidden[(size_t)(st * 2 + 1) * BATCH * H_DIM + ob] = cp4;
        *(float4*)&out_lstm  [(size_t)st * BATCH * H_DIM + ob]           = hn4;
        *(float4*)&g_h[(st + 1) & 1][ob]                                 = hn4;

        grid_sync();
    }
}

// ---------------- launch ---------------------------------------------------
extern "C" void kernel_launch(void* const* d_in, const int* in_sizes, int n_in,
                              void* d_out, int out_size) {
    const float* x     = (const float*)d_in[0];
    const int*   dones = (const int*)  d_in[1];
    const float* Wih   = (const float*)d_in[2];
    const float* Whh   = (const float*)d_in[3];
    const float* bih   = (const float*)d_in[4];
    const float* bhh   = (const float*)d_in[5];

    float* out_lstm   = (float*)d_out;
    float* out_hidden = out_lstm + (size_t)T_STEPS * BATCH * H_DIM;

    const int smem_xg   = AP_WORDS * 4;                      // 98304 B
    const int smem_lstm = (AP_WORDS + 4 * 32 * 36) * 4;      // 116736 B
    cudaFuncSetAttribute(xgemm_tc, cudaFuncAttributeMaxDynamicSharedMemorySize,
                         smem_xg);
    cudaFuncSetAttribute(lstm_tc, cudaFuncAttributeMaxDynamicSharedMemorySize,
                         smem_lstm);

    prep_kernel<<<8192, 256>>>(Wih, Whh);

    dim3 gx(GATES / 128, (T_STEPS * BATCH) / 32);            // (16, 2048)
    xgemm_tc<<<gx, 256, smem_xg>>>(x, bih, bhh);

    lstm_tc<<<NBLK, 256, smem_lstm>>>(dones, out_lstm, out_hidden);
}

// round 4
// speedup vs baseline: 2.4373x; 1.0015x over previous
#include <cuda_runtime.h>
#include <math.h>
#include <stdint.h>

#define T_STEPS 256
#define BATCH   256
#define IN_DIM  512
#define H_DIM   512
#define GATES   2048
#define NBLK    128

// ---------------- device scratch (no allocs allowed) ----------------------
__device__ float g_Xg[(size_t)T_STEPS * BATCH * GATES];    // x @ Wih^T + b (512MB)
__device__ float g_h[2][BATCH * H_DIM];                    // double-buffered hidden
__device__ float g_Wp_hh[64 * 2048 * 8];                   // tf32-packed W_hh frags
__device__ float g_Wp_ih[64 * 2048 * 8];                   // tf32-packed W_ih frags
__device__ unsigned g_bar_count = 0;
__device__ volatile unsigned g_bar_gen = 0;

// ---------------- helpers --------------------------------------------------
__device__ __forceinline__ float f2tf32f(float f) {
    unsigned r;
    asm("cvt.rna.tf32.f32 %0, %1;" : "=r"(r) : "f"(f));
    return __uint_as_float(r);
}

__device__ __forceinline__ void mma_tf32(float* c,
    unsigned a0, unsigned a1, unsigned a2, unsigned a3,
    unsigned b0, unsigned b1)
{
    asm volatile(
        "mma.sync.aligned.m16n8k8.row.col.f32.tf32.tf32.f32 "
        "{%0,%1,%2,%3},{%4,%5,%6,%7},{%8,%9},{%0,%1,%2,%3};"
        : "+f"(c[0]), "+f"(c[1]), "+f"(c[2]), "+f"(c[3])
        : "r"(a0), "r"(a1), "r"(a2), "r"(a3), "r"(b0), "r"(b1));
}

__device__ __forceinline__ float sigm(float v) { return 1.0f / (1.0f + expf(-v)); }

// ---------------- prep: pack W into tf32 fragment order -------------------
// Wp[kb][n][p][hi] = tf32(W[n][kb*8 + p + 4*hi]),  p=k%4, hi=(k%8)/4
__global__ void prep_kernel(const float* __restrict__ Wih,
                            const float* __restrict__ Whh) {
    int idx = blockIdx.x * blockDim.x + threadIdx.x;   // 0 .. 2*2^20-1
    int which = idx >> 20;
    int r = idx & 1048575;          // n*512 + k
    int n = r >> 9, k = r & 511;
    const float* W = which ? Whh : Wih;
    float* dst = which ? g_Wp_hh : g_Wp_ih;
    int kb = k >> 3, p = k & 3, hi = (k >> 2) & 1;
    dst[(((size_t)kb * 2048 + n) * 4 + p) * 2 + hi] = f2tf32f(W[r]);
}

// ---------------- A-tile staging into fragment-permuted smem --------------
// Ap layout: [kb(64)][lane(32)][12 pad]  (j = 4*mt + 2*jk + b8) -> one
// LDS.128 per m16 fragment, conflict-free (stride 12 words).
// thread t stages row b=t/8, k-range (t%8)*64..+63.
#define AP_WORDS (64 * 32 * 12)

template <bool ZERO, bool CG>
__device__ __forceinline__ void stage_A(float* Ap, const float* src_row,
                                        float scale, int tid) {
    int b  = tid >> 3;
    int kc = tid & 7;
    const float4* src = (const float4*)(src_row + kc * 64);
    #pragma unroll
    for (int v = 0; v < 16; v++) {
        float4 hv;
        if (ZERO) hv = make_float4(0.f, 0.f, 0.f, 0.f);
        else if (CG) hv = __ldcg(src + v);
        else hv = __ldg(src + v);
        float vals[4] = {hv.x * scale, hv.y * scale, hv.z * scale, hv.w * scale};
        int kbase = kc * 64 + v * 4;
        #pragma unroll
        for (int e = 0; e < 4; e++) {
            int k = kbase + e;
            int kb = k >> 3;
            int l  = ((b & 7) << 2) | (k & 3);
            int j  = ((b >> 4) << 2) | (((k >> 2) & 1) << 1) | ((b >> 3) & 1);
            Ap[(kb * 32 + l) * 12 + j] = f2tf32f(vals[e]);
        }
    }
}

// ---------------- kernel 1: Xg = x @ Wih^T + (bih+bhh), tf32 MMA ----------
// block tile: m=32 rows of x, n=128 cols. 8 warps: warp w -> n range w*16.
extern __shared__ float sm_dyn[];

__global__ __launch_bounds__(256, 2) void xgemm_tc(
    const float* __restrict__ x,
    const float* __restrict__ bih,
    const float* __restrict__ bhh)
{
    float* Ap = sm_dyn;
    const int tid = threadIdx.x, lane = tid & 31, w = tid >> 5;
    const int n0 = blockIdx.x * 128;
    const int m0 = blockIdx.y * 32;

    stage_A<false, false>(Ap, x + (size_t)(m0 + (tid >> 3)) * IN_DIM, 1.0f, tid);
    __syncthreads();

    float acc[2][2][4] = {};          // [mt][nt][creg]
    const int nw = n0 + w * 16;
    const float2* Wp = (const float2*)g_Wp_ih;

    #pragma unroll 4
    for (int kb = 0; kb < 64; kb++) {
        float4 A0 = *(float4*)&Ap[(kb * 32 + lane) * 12];
        float4 A1 = *(float4*)&Ap[(kb * 32 + lane) * 12 + 4];
        unsigned a0x = __float_as_uint(A0.x), a0y = __float_as_uint(A0.y);
        unsigned a0z = __float_as_uint(A0.z), a0w = __float_as_uint(A0.w);
        unsigned a1x = __float_as_uint(A1.x), a1y = __float_as_uint(A1.y);
        unsigned a1z = __float_as_uint(A1.z), a1w = __float_as_uint(A1.w);
        #pragma unroll
        for (int nt = 0; nt < 2; nt++) {
            int n = nw + nt * 8 + (lane >> 2);
            float2 bv = Wp[((size_t)kb * 2048 + n) * 4 + (lane & 3)];
            unsigned b0 = __float_as_uint(bv.x), b1 = __float_as_uint(bv.y);
            mma_tf32(acc[0][nt], a0x, a0y, a0z, a0w, b0, b1);
            mma_tf32(acc[1][nt], a1x, a1y, a1z, a1w, b0, b1);
        }
    }

    #pragma unroll
    for (int nt = 0; nt < 2; nt++) {
        int nc = nw + nt * 8 + (lane & 3) * 2;
        float bs0 = __ldg(&bih[nc]) + __ldg(&bhh[nc]);
        float bs1 = __ldg(&bih[nc + 1]) + __ldg(&bhh[nc + 1]);
        #pragma unroll
        for (int mt = 0; mt < 2; mt++) {
            int r0 = m0 + mt * 16 + (lane >> 2);
            float2 v0 = make_float2(acc[mt][nt][0] + bs0, acc[mt][nt][1] + bs1);
            float2 v1 = make_float2(acc[mt][nt][2] + bs0, acc[mt][nt][3] + bs1);
            *(float2*)&g_Xg[(size_t)r0 * GATES + nc]        = v0;
            *(float2*)&g_Xg[(size_t)(r0 + 8) * GATES + nc]  = v1;
        }
    }
}

// ---------------- grid-wide barrier (all 128 blocks resident) -------------
__device__ __forceinline__ void grid_sync() {
    __syncthreads();
    if (threadIdx.x == 0) {
        __threadfence();
        unsigned snap = g_bar_gen;
        unsigned arrived = atomicAdd(&g_bar_count, 1u);
        if (arrived == gridDim.x - 1) {
            g_bar_count = 0;
            __threadfence();
            g_bar_gen = snap + 1;
        } else {
            while (g_bar_gen == snap) __nanosleep(32);
        }
    }
    __syncthreads();
}

// ---------------- kernel 2: persistent LSTM recurrence --------------------
// 128 blocks = 16 hh-tiles x 8 b-tiles, each 32b x 32hh x 4 gates.
// 8 warps: warp w -> (gate pair gp=w>>2, hh group hg=w&3), m=32 (2 m16 frags).
// c and h state live in registers (block owns its tile). h exchanged via
// global double buffer + grid barrier each step.
__global__ __launch_bounds__(256, 1) void lstm_tc(
    const int*  __restrict__ dones,
    float* __restrict__ out_lstm,       // [T,B,H]
    float* __restrict__ out_hidden)     // [T,2,B,H]
{
    float* Ap  = sm_dyn;                 // 24576 words
    float* Acc = sm_dyn + AP_WORDS;      // [4][32][36] words

    const int tid = threadIdx.x, lane = tid & 31, w = tid >> 5;
    const int hh0 = (blockIdx.x & 15) * 32;
    const int b0  = (blockIdx.x >> 4) * 32;
    const int gp = w >> 2, hg = w & 3;
    const int eb  = tid >> 3;            // epilogue row (== staging row)
    const int ehh = (tid & 7) * 4;       // epilogue 4 consecutive hh

    float h_st[4] = {0.f, 0.f, 0.f, 0.f};
    float c_st[4] = {0.f, 0.f, 0.f, 0.f};

    const float2* Wp = (const float2*)g_Wp_hh;

    for (int st = 0; st < T_STEPS; st++) {
        // prefetch xg + done mask for epilogue (hidden under the k-loop)
        float4 xv[4];
        {
            const float* xg = g_Xg + ((size_t)st * BATCH + (b0 + eb)) * GATES
                            + hh0 + ehh;
            #pragma unroll
            for (int g = 0; g < 4; g++)
                xv[g] = __ldg((const float4*)(xg + g * 512));
        }
        const float keep = 1.0f - (float)__ldg(&dones[st * BATCH + b0 + eb]);

        // stage masked h into fragment-permuted smem (L2-only: L1 is stale)
        if (st == 0)
            stage_A<true, true>(Ap, (const float*)0, 0.0f, tid);
        else
            stage_A<false, true>(Ap,
                g_h[st & 1] + (size_t)(b0 + eb) * H_DIM, keep, tid);
        __syncthreads();

        float acc[2][2][4] = {};         // [gate-in-pair][mt][creg]
        #pragma unroll 4
        for (int kb = 0; kb < 64; kb++) {
            float4 A0 = *(float4*)&Ap[(kb * 32 + lane) * 12];
            float4 A1 = *(float4*)&Ap[(kb * 32 + lane) * 12 + 4];
            unsigned a0x = __float_as_uint(A0.x), a0y = __float_as_uint(A0.y);
            unsigned a0z = __float_as_uint(A0.z), a0w = __float_as_uint(A0.w);
            unsigned a1x = __float_as_uint(A1.x), a1y = __float_as_uint(A1.y);
            unsigned a1z = __float_as_uint(A1.z), a1w = __float_as_uint(A1.w);
            #pragma unroll
            for (int gi = 0; gi < 2; gi++) {
                int n = (gp * 2 + gi) * 512 + hh0 + hg * 8 + (lane >> 2);
                float2 bv = Wp[((size_t)kb * 2048 + n) * 4 + (lane & 3)];
                unsigned b0r = __float_as_uint(bv.x), b1r = __float_as_uint(bv.y);
                mma_tf32(acc[gi][0], a0x, a0y, a0z, a0w, b0r, b1r);
                mma_tf32(acc[gi][1], a1x, a1y, a1z, a1w, b0r, b1r);
            }
        }

        // exchange accumulators through smem so each thread gets all 4 gates
        #pragma unroll
        for (int gi = 0; gi < 2; gi++) {
            int g  = gp * 2 + gi;
            int hc = hg * 8 + (lane & 3) * 2;
            #pragma unroll
            for (int mt = 0; mt < 2; mt++) {
                int bl = mt * 16 + (lane >> 2);
                *(float2*)&Acc[(g * 32 + bl) * 36 + hc] =
                    make_float2(acc[gi][mt][0], acc[gi][mt][1]);
                *(float2*)&Acc[(g * 32 + bl + 8) * 36 + hc] =
                    make_float2(acc[gi][mt][2], acc[gi][mt][3]);
            }
        }
        __syncthreads();

        // epilogue: thread owns (b0+eb, hh0+ehh..+3); state in registers
        float4 ag[4];
        #pragma unroll
        for (int g = 0; g < 4; g++)
            ag[g] = *(float4*)&Acc[(g * 32 + eb) * 36 + ehh];

        float4 hp4, cp4, hn4;
        float* hpf = &hp4.x; float* cpf = &cp4.x; float* hnf = &hn4.x;
        #pragma unroll
        for (int i = 0; i < 4; i++) {
            float gv_i = ((float*)&ag[0])[i] + ((float*)&xv[0])[i];
            float gv_f = ((float*)&ag[1])[i] + ((float*)&xv[1])[i];
            float gv_g = ((float*)&ag[2])[i] + ((float*)&xv[2])[i];
            float gv_o = ((float*)&ag[3])[i] + ((float*)&xv[3])[i];

            float hpv = h_st[i] * keep;
            float cpv = c_st[i] * keep;

            float ii = sigm(gv_i);
            float ff = sigm(gv_f);
            float gg = tanhf(gv_g);
            float oo = sigm(gv_o);

            float cnv = ff * cpv + ii * gg;
            float hnv = oo * tanhf(cnv);

            h_st[i] = hnv; c_st[i] = cnv;
            hpf[i] = hpv; cpf[i] = cpv; hnf[i] = hnv;
        }

        const size_t ob = (size_t)(b0 + eb) * H_DIM + hh0 + ehh;
        *(float4*)&out_hidden[(size_t)(st * 2 + 0) * BATCH * H_DIM + ob] = hp4;
        *(float4*)&out_hidden[(size_t)(st * 2 + 1) * BATCH * H_DIM + ob] = cp4;
        *(float4*)&out_lstm  [(size_t)st * BATCH * H_DIM + ob]           = hn4;
        *(float4*)&g_h[(st + 1) & 1][ob]                                 = hn4;

        grid_sync();
    }
}

// ---------------- launch ---------------------------------------------------
extern "C" void kernel_launch(void* const* d_in, const int* in_sizes, int n_in,
                              void* d_out, int out_size) {
    const float* x     = (const float*)d_in[0];
    const int*   dones = (const int*)  d_in[1];
    const float* Wih   = (const float*)d_in[2];
    const float* Whh   = (const float*)d_in[3];
    const float* bih   = (const float*)d_in[4];
    const float* bhh   = (const float*)d_in[5];

    float* out_lstm   = (float*)d_out;
    float* out_hidden = out_lstm + (size_t)T_STEPS * BATCH * H_DIM;

    const int smem_xg   = AP_WORDS * 4;                      // 98304 B
    const int smem_lstm = (AP_WORDS + 4 * 32 * 36) * 4;      // 116736 B
    cudaFuncSetAttribute(xgemm_tc, cudaFuncAttributeMaxDynamicSharedMemorySize,
                         smem_xg);
    cudaFuncSetAttribute(lstm_tc, cudaFuncAttributeMaxDynamicSharedMemorySize,
                         smem_lstm);

    prep_kernel<<<8192, 256>>>(Wih, Whh);

    dim3 gx(GATES / 128, (T_STEPS * BATCH) / 32);            // (16, 2048)
    xgemm_tc<<<gx, 256, smem_xg>>>(x, bih, bhh);

    lstm_tc<<<NBLK, 256, smem_lstm>>>(dones, out_lstm, out_hidden);
}

// round 5
// speedup vs baseline: 3.8194x; 1.5670x over previous
#include <cuda_runtime.h>
#include <cuda_fp16.h>
#include <math.h>
#include <stdint.h>

#define T_STEPS 256
#define BATCH   256
#define IN_DIM  512
#define H_DIM   512
#define GATES   2048

// ---------------- device scratch -------------------------------------------
__device__ float    g_Xg[(size_t)T_STEPS * BATCH * GATES];   // x@Wih^T + b
__device__ float    g_Wp_ih[64 * 2048 * 8];                  // tf32 frags (xgemm)
__device__ unsigned g_Wph[16 * 4 * 4 * 32 * 32 * 2];         // fp16 W_hh frags (2MB)
__device__ unsigned g_APg[2 * 8 * 32 * 2 * 32 * 4];          // fp16 h frags, dbl-buf
__device__ unsigned g_cnt[8 * 32];                           // per-group barrier
__device__ volatile unsigned g_gen[8 * 32];

// ---------------- helpers --------------------------------------------------
__device__ __forceinline__ float f2tf32f(float f) {
    unsigned r;
    asm("cvt.rna.tf32.f32 %0, %1;" : "=r"(r) : "f"(f));
    return __uint_as_float(r);
}

__device__ __forceinline__ void mma_tf32(float* c,
    unsigned a0, unsigned a1, unsigned a2, unsigned a3,
    unsigned b0, unsigned b1)
{
    asm volatile(
        "mma.sync.aligned.m16n8k8.row.col.f32.tf32.tf32.f32 "
        "{%0,%1,%2,%3},{%4,%5,%6,%7},{%8,%9},{%0,%1,%2,%3};"
        : "+f"(c[0]), "+f"(c[1]), "+f"(c[2]), "+f"(c[3])
        : "r"(a0), "r"(a1), "r"(a2), "r"(a3), "r"(b0), "r"(b1));
}

__device__ __forceinline__ void mma_f16(float* c, uint4 A, uint2 B) {
    asm volatile(
        "mma.sync.aligned.m16n8k16.row.col.f32.f16.f16.f32 "
        "{%0,%1,%2,%3},{%4,%5,%6,%7},{%8,%9},{%0,%1,%2,%3};"
        : "+f"(c[0]), "+f"(c[1]), "+f"(c[2]), "+f"(c[3])
        : "r"(A.x), "r"(A.y), "r"(A.z), "r"(A.w), "r"(B.x), "r"(B.y));
}

__device__ __forceinline__ float sigm(float v) { return 1.0f / (1.0f + expf(-v)); }

// ---------------- prep: tf32 frags for Wih (xgemm path) -------------------
__global__ void prep_ih(const float* __restrict__ Wih) {
    int idx = blockIdx.x * blockDim.x + threadIdx.x;   // < 2^20
    int n = idx >> 9, k = idx & 511;
    int kb = k >> 3, p = k & 3, hi = (k >> 2) & 1;
    g_Wp_ih[(((size_t)kb * 2048 + n) * 4 + p) * 2 + hi] = f2tf32f(Wih[idx]);
}

// ---------------- prep: fp16 B-fragments for W_hh -------------------------
// frag value at (k,n) = Whh[n][k]; layout [ht][g][hg][kb16][lane][reg] (b32)
__global__ void prep_hh(const float* __restrict__ Whh) {
    int t = blockIdx.x * blockDim.x + threadIdx.x;     // < 2^19
    int n = t >> 8, kp = t & 255, k = kp * 2;
    float2 wv = ((const float2*)Whh)[(size_t)n * 256 + kp];
    __half2 h2 = __floats2half2_rn(wv.x, wv.y);        // low = even k
    int g  = n >> 9, hh = n & 511;
    int ht = hh >> 5, hg = (hh >> 3) & 3;
    int kb16 = k >> 4;
    int lanei = ((n & 7) << 2) | ((k & 7) >> 1);
    int reg = (k >> 3) & 1;
    size_t bi = ((((size_t)(ht * 4 + g) * 4 + hg) * 32 + kb16) * 32 + lanei) * 2 + reg;
    g_Wph[bi] = *(unsigned*)&h2;
}

// ---------------- xgemm (unchanged tf32 path) ------------------------------
#define AP_WORDS (64 * 32 * 12)
extern __shared__ float sm_dyn[];

template <bool ZERO>
__device__ __forceinline__ void stage_A_x(float* Ap, const float* src_row, int tid) {
    int b  = tid >> 3;
    int kc = tid & 7;
    const float4* src = (const float4*)(src_row + kc * 64);
    #pragma unroll
    for (int v = 0; v < 16; v++) {
        float4 hv = ZERO ? make_float4(0.f,0.f,0.f,0.f) : __ldg(src + v);
        float vals[4] = {hv.x, hv.y, hv.z, hv.w};
        int kbase = kc * 64 + v * 4;
        #pragma unroll
        for (int e = 0; e < 4; e++) {
            int k = kbase + e;
            int kb = k >> 3;
            int l  = ((b & 7) << 2) | (k & 3);
            int j  = ((b >> 4) << 2) | (((k >> 2) & 1) << 1) | ((b >> 3) & 1);
            Ap[(kb * 32 + l) * 12 + j] = f2tf32f(vals[e]);
        }
    }
}

__global__ __launch_bounds__(256, 2) void xgemm_tc(
    const float* __restrict__ x,
    const float* __restrict__ bih,
    const float* __restrict__ bhh)
{
    float* Ap = sm_dyn;
    const int tid = threadIdx.x, lane = tid & 31, w = tid >> 5;
    const int n0 = blockIdx.x * 128;
    const int m0 = blockIdx.y * 32;

    stage_A_x<false>(Ap, x + (size_t)(m0 + (tid >> 3)) * IN_DIM, tid);
    __syncthreads();

    float acc[2][2][4] = {};
    const int nw = n0 + w * 16;
    const float2* Wp = (const float2*)g_Wp_ih;

    #pragma unroll 4
    for (int kb = 0; kb < 64; kb++) {
        float4 A0 = *(float4*)&Ap[(kb * 32 + lane) * 12];
        float4 A1 = *(float4*)&Ap[(kb * 32 + lane) * 12 + 4];
        unsigned a0x = __float_as_uint(A0.x), a0y = __float_as_uint(A0.y);
        unsigned a0z = __float_as_uint(A0.z), a0w = __float_as_uint(A0.w);
        unsigned a1x = __float_as_uint(A1.x), a1y = __float_as_uint(A1.y);
        unsigned a1z = __float_as_uint(A1.z), a1w = __float_as_uint(A1.w);
        #pragma unroll
        for (int nt = 0; nt < 2; nt++) {
            int n = nw + nt * 8 + (lane >> 2);
            float2 bv = Wp[((size_t)kb * 2048 + n) * 4 + (lane & 3)];
            unsigned b0 = __float_as_uint(bv.x), b1 = __float_as_uint(bv.y);
            mma_tf32(acc[0][nt], a0x, a0y, a0z, a0w, b0, b1);
            mma_tf32(acc[1][nt], a1x, a1y, a1z, a1w, b0, b1);
        }
    }

    #pragma unroll
    for (int nt = 0; nt < 2; nt++) {
        int nc = nw + nt * 8 + (lane & 3) * 2;
        float bs0 = __ldg(&bih[nc]) + __ldg(&bhh[nc]);
        float bs1 = __ldg(&bih[nc + 1]) + __ldg(&bhh[nc + 1]);
        #pragma unroll
        for (int mt = 0; mt < 2; mt++) {
            int r0 = m0 + mt * 16 + (lane >> 2);
            float2 v0 = make_float2(acc[mt][nt][0] + bs0, acc[mt][nt][1] + bs1);
            float2 v1 = make_float2(acc[mt][nt][2] + bs0, acc[mt][nt][3] + bs1);
            __stcs((float2*)&g_Xg[(size_t)r0 * GATES + nc], v0);
            __stcs((float2*)&g_Xg[(size_t)(r0 + 8) * GATES + nc], v1);
        }
    }
}

// ---------------- per-group barrier (16 blocks sharing a b-tile) -----------
__device__ __forceinline__ void group_sync(int grp) {
    __threadfence();                 // make this thread's STGs L2-visible
    __syncthreads();
    if (threadIdx.x == 0) {
        unsigned snap = g_gen[grp * 32];
        if (atomicAdd(&g_cnt[grp * 32], 1u) == 15u) {
            g_cnt[grp * 32] = 0;
            __threadfence();
            g_gen[grp * 32] = snap + 1;
        } else {
            while (g_gen[grp * 32] == snap) __nanosleep(20);
        }
    }
    __syncthreads();
}

// ---------------- persistent LSTM recurrence (fp16 MMA, W in smem) ---------
// 128 blocks = 8 b-groups x 16 hh-tiles. Block tile: 32 b x 32 hh x 4 gates.
// W_hh slice (128KB fp16 frags) resident in smem for the whole kernel.
// h exchanged as pre-packed fp16 A-fragments via L2 (32KB copy/step/block).
__global__ __launch_bounds__(256, 1) void lstm_tc(
    const int*  __restrict__ dones,
    float* __restrict__ out_lstm,       // [T,B,H]
    float* __restrict__ out_hidden)     // [T,2,B,H]
{
    unsigned* Ws  = (unsigned*)sm_dyn;          // 32768 u32 (128KB)
    unsigned* APs = Ws + 32768;                 // 8192 u32  (32KB)
    float*    Acc = (float*)(APs + 8192);       // 4608 f32  (18KB)

    const int tid = threadIdx.x, lane = tid & 31, w = tid >> 5;
    const int ht = blockIdx.x & 15, bt = blockIdx.x >> 4;
    const int hh0 = ht * 32, b0 = bt * 32;
    const int gp = w >> 2, hg = w & 3;
    const int eb  = tid >> 3;          // epilogue batch row 0..31
    const int ehh = (tid & 7) * 4;     // epilogue 4 consecutive hh

    // load W slice into smem once (verbatim fragment copy)
    {
        const uint4* src = (const uint4*)(g_Wph + (size_t)ht * 32768);
        uint4* dst = (uint4*)Ws;
        #pragma unroll
        for (int i = 0; i < 32; i++) dst[tid + i * 256] = src[tid + i * 256];
    }
    __syncthreads();

    float h_st[4] = {0.f,0.f,0.f,0.f};
    float c_st[4] = {0.f,0.f,0.f,0.f};

    for (int st = 0; st < T_STEPS; st++) {
        // prefetch Xg + done mask (overlaps with k-loop)
        float4 xv[4];
        const float* xg = g_Xg + ((size_t)st * BATCH + (b0 + eb)) * GATES + hh0 + ehh;
        #pragma unroll
        for (int g = 0; g < 4; g++) xv[g] = __ldcs((const float4*)(xg + g * H_DIM));
        const float keep = 1.0f - (float)__ldg(&dones[st * BATCH + b0 + eb]);

        float4 ag[4];
        if (st == 0) {
            #pragma unroll
            for (int g = 0; g < 4; g++) ag[g] = make_float4(0.f,0.f,0.f,0.f);
        } else {
            // copy A fragments (32KB) from L2 into smem
            const uint4* asrc = (const uint4*)(g_APg + ((size_t)(st & 1) * 8 + bt) * 8192);
            uint4* adst = (uint4*)APs;
            #pragma unroll
            for (int i = 0; i < 8; i++)
                adst[tid + i * 256] = __ldcg(asrc + tid + i * 256);
            __syncthreads();

            float acc[2][2][4] = {};       // [gi][mt][creg]
            #pragma unroll 4
            for (int kb = 0; kb < 32; kb++) {
                uint4 A0 = *(const uint4*)&APs[((kb * 2 + 0) * 32 + lane) * 4];
                uint4 A1 = *(const uint4*)&APs[((kb * 2 + 1) * 32 + lane) * 4];
                #pragma unroll
                for (int gi = 0; gi < 2; gi++) {
                    int nb = (gp * 2 + gi) * 4 + hg;
                    uint2 B = *(const uint2*)&Ws[((nb * 32 + kb) * 32 + lane) * 2];
                    mma_f16(acc[gi][0], A0, B);
                    mma_f16(acc[gi][1], A1, B);
                }
            }

            // exchange accumulators so each thread gets all 4 gates
            #pragma unroll
            for (int gi = 0; gi < 2; gi++) {
                int g  = gp * 2 + gi;
                int hc = hg * 8 + (lane & 3) * 2;
                #pragma unroll
                for (int mt = 0; mt < 2; mt++) {
                    int bl = mt * 16 + (lane >> 2);
                    *(float2*)&Acc[(g * 32 + bl) * 36 + hc] =
                        make_float2(acc[gi][mt][0], acc[gi][mt][1]);
                    *(float2*)&Acc[(g * 32 + bl + 8) * 36 + hc] =
                        make_float2(acc[gi][mt][2], acc[gi][mt][3]);
                }
            }
            __syncthreads();
            #pragma unroll
            for (int g = 0; g < 4; g++)
                ag[g] = *(const float4*)&Acc[(g * 32 + eb) * 36 + ehh];
        }

        // epilogue: gates -> state update; state lives in registers
        float4 hp4, cp4, hn4;
        float* hpf = &hp4.x; float* cpf = &cp4.x; float* hnf = &hn4.x;
        #pragma unroll
        for (int i = 0; i < 4; i++) {
            float gv_i = ((float*)&ag[0])[i] + ((float*)&xv[0])[i];
            float gv_f = ((float*)&ag[1])[i] + ((float*)&xv[1])[i];
            float gv_g = ((float*)&ag[2])[i] + ((float*)&xv[2])[i];
            float gv_o = ((float*)&ag[3])[i] + ((float*)&xv[3])[i];

            float hpv = h_st[i] * keep;
            float cpv = c_st[i] * keep;

            float ii = sigm(gv_i);
            float ff = sigm(gv_f);
            float gg = tanhf(gv_g);
            float oo = sigm(gv_o);

            float cnv = ff * cpv + ii * gg;
            float hnv = oo * tanhf(cnv);

            h_st[i] = hnv; c_st[i] = cnv;
            hpf[i] = hpv; cpf[i] = cpv; hnf[i] = hnv;
        }

        const size_t ob = (size_t)(b0 + eb) * H_DIM + hh0 + ehh;
        __stcs((float4*)&out_hidden[(size_t)(st * 2 + 0) * BATCH * H_DIM + ob], hp4);
        __stcs((float4*)&out_hidden[(size_t)(st * 2 + 1) * BATCH * H_DIM + ob], cp4);
        __stcs((float4*)&out_lstm  [(size_t)st * BATCH * H_DIM + ob],           hn4);

        if (st < T_STEPS - 1) {
            // store h*keep(st+1) as fp16 A-fragments for next step
            float kn = 1.0f - (float)__ldg(&dones[(st + 1) * BATCH + b0 + eb]);
            __half2 w0 = __floats2half2_rn(h_st[0] * kn, h_st[1] * kn);
            __half2 w1 = __floats2half2_rn(h_st[2] * kn, h_st[3] * kn);
            int k0   = hh0 + ehh;
            int kb16 = k0 >> 4;
            int mt   = eb >> 4;
            int reg  = ((eb >> 3) & 1) + (((k0 >> 3) & 1) << 1);
            int l0   = ((eb & 7) << 2) | ((k0 >> 1) & 3);
            unsigned* apd = g_APg +
                ((((size_t)((st + 1) & 1) * 8 + bt) * 32 + kb16) * 2 + mt) * 128;
            apd[l0 * 4 + reg]       = *(unsigned*)&w0;
            apd[(l0 + 1) * 4 + reg] = *(unsigned*)&w1;

            group_sync(bt);
        }
    }
}

// ---------------- launch ----------------------------------------------------
extern "C" void kernel_launch(void* const* d_in, const int* in_sizes, int n_in,
                              void* d_out, int out_size) {
    const float* x     = (const float*)d_in[0];
    const int*   dones = (const int*)  d_in[1];
    const float* Wih   = (const float*)d_in[2];
    const float* Whh   = (const float*)d_in[3];
    const float* bih   = (const float*)d_in[4];
    const float* bhh   = (const float*)d_in[5];

    float* out_lstm   = (float*)d_out;
    float* out_hidden = out_lstm + (size_t)T_STEPS * BATCH * H_DIM;

    const int smem_xg   = AP_WORDS * 4;                       // 98304 B
    const int smem_lstm = (32768 + 8192 + 4608) * 4;          // 182272 B
    cudaFuncSetAttribute(xgemm_tc, cudaFuncAttributeMaxDynamicSharedMemorySize,
                         smem_xg);
    cudaFuncSetAttribute(lstm_tc, cudaFuncAttributeMaxDynamicSharedMemorySize,
                         smem_lstm);

    prep_ih<<<4096, 256>>>(Wih);
    prep_hh<<<2048, 256>>>(Whh);

    dim3 gx(GATES / 128, (T_STEPS * BATCH) / 32);             // (16, 2048)
    xgemm_tc<<<gx, 256, smem_xg>>>(x, bih, bhh);

    lstm_tc<<<128, 256, smem_lstm>>>(dones, out_lstm, out_hidden);
}